// round 8
// baseline (speedup 1.0000x reference)
#include <cuda_runtime.h>
#include <cuda_fp16.h>
#include <cstdint>

// out[loc0]       = feat0 @ W0   (M=262144, K=512, N=128) fp16 mma.sync, err ~2.3e-4
// out[loc1++loc2] = emb[node_ids[loc]]
// Barrier-free GEMM; B fragments packed per-lane-contiguous so each warp fetches
// them with 4x LDG.128 per kstep (was 16x LDG.32) -> L1 wavefront pressure -60%.
// Fused grid: even blocks = GEMM tile (64 rows), odd = gather slice (192 rows).

#define KDIM 512
#define NDIM 128
#define BM   64
#define NCHUNK 16                 // K chunks of 32
#define NGEMM 4096                // M/BM
#define GRID  (2 * NGEMM)

// B table: idx = (((c*2+s2)*2+wn)*32 + lane)*16 + nf*2 + reg   (128 KB)
// holds B[k0 + reg*8 + (lane&3)*2 + {0,1}][ (wn*8+nf)*8 + lane/4 ],  k0=(c*2+s2)*16
__device__ __align__(16) uint32_t g_Bfrag[32768];

// ------------------------------------------------------------- helpers
__device__ __forceinline__ void mma_f16(float* d, const uint32_t* a, const uint32_t* b) {
    asm volatile(
        "mma.sync.aligned.m16n8k16.row.col.f32.f16.f16.f32 "
        "{%0,%1,%2,%3}, {%4,%5,%6,%7}, {%8,%9}, {%0,%1,%2,%3};"
        : "+f"(d[0]), "+f"(d[1]), "+f"(d[2]), "+f"(d[3])
        : "r"(a[0]), "r"(a[1]), "r"(a[2]), "r"(a[3]), "r"(b[0]), "r"(b[1]));
}
__device__ __forceinline__ uint32_t f2h2(float2 v) {
    __half2 p = __floats2half2_rn(v.x, v.y);
    return *reinterpret_cast<uint32_t*>(&p);
}

// --------------------------------------------------- W0 -> fp16 fragment table
__global__ void convert_w_kernel(const float* __restrict__ W0) {
    int idx = blockIdx.x * 256 + threadIdx.x;   // 0..32767
    int reg  = idx & 1;
    int nf   = (idx >> 1) & 7;
    int lane = (idx >> 4) & 31;
    int wn   = (idx >> 9) & 1;
    int s    = idx >> 10;                       // kstep 0..31 (= c*2+s2)
    int n = (wn * 8 + nf) * 8 + (lane >> 2);
    int k = s * 16 + reg * 8 + (lane & 3) * 2;
    float x0 = W0[(size_t)k * NDIM + n];
    float x1 = W0[(size_t)(k + 1) * NDIM + n];
    __half2 p = __halves2half2(__float2half_rn(x0), __float2half_rn(x1));
    g_Bfrag[idx] = *reinterpret_cast<uint32_t*>(&p);
}

// --------------------------------------------------------------- fused kernel
__global__ void __launch_bounds__(256, 3)
fused_kernel(const float* __restrict__ feat0,
             const int* __restrict__ loc0,
             const int* __restrict__ node_ids,
             const int* __restrict__ loc1, const int* __restrict__ loc2,
             const float* __restrict__ emb,
             float* __restrict__ out,
             int n1, int n2) {
    const int tid  = threadIdx.x;
    const int wid  = tid >> 5;
    const int lane = tid & 31;

    if (blockIdx.x & 1) {
        // ===================== gather slice (12-deep MLP) ==================
        const int ntot = n1 + n2;
        const int gb   = blockIdx.x >> 1;                 // 0..NGEMM-1
        const int rpb  = (ntot + NGEMM - 1) / NGEMM;      // rows per block (192)
        const int rpw  = (rpb + 7) / 8;                   // rows per warp (24)
        long rbase = (long)gb * rpb + (long)wid * rpw;
        for (int i = 0; i < rpw; i += 12) {
            int l[12];
#pragma unroll
            for (int r = 0; r < 12; r++) {
                long row = rbase + i + r;
                l[r] = (row < (long)ntot && (i + r) < rpw)
                         ? ((row < (long)n1) ? loc1[row] : loc2[row - n1]) : -1;
            }
            int nid[12];
#pragma unroll
            for (int r = 0; r < 12; r++) nid[r] = (l[r] >= 0) ? node_ids[l[r]] : 0;
            float4 v[12];
#pragma unroll
            for (int r = 0; r < 12; r++)
                if (l[r] >= 0)
                    v[r] = __ldcs(((const float4*)(emb + (size_t)nid[r] * NDIM)) + lane);
#pragma unroll
            for (int r = 0; r < 12; r++)
                if (l[r] >= 0)
                    __stcs(((float4*)(out + (size_t)l[r] * NDIM)) + lane, v[r]);
        }
        return;
    }

    // ========================= GEMM tile (64 x 128) ========================
    // 8 warps: wm = wid>>1 (0..3, 16 rows each), wn = wid&1 (0..1, 64 cols each)
    const int wm = wid >> 1;
    const int wn = wid & 1;
    const int m0 = (blockIdx.x >> 1) * BM;
    const int rowbase = m0 + wm * 16 + (lane >> 2);       // fragment row g

    // A row pointers for rows g and g+8, at k base (lane&3)*2
    const float* a0 = feat0 + (size_t)rowbase * KDIM + (lane & 3) * 2;
    const float* a1 = a0 + 8 * KDIM;
    // per-lane B base for this warp's wn half
    const uint4* bBase = (const uint4*)(g_Bfrag + ((size_t)wn * 32 + lane) * 16);

    float acc[8][4];
#pragma unroll
    for (int nf = 0; nf < 8; ++nf)
#pragma unroll
        for (int i = 0; i < 4; ++i) acc[nf][i] = 0.f;

    // raw A prefetch for chunk 0: [s2*4+i] with k = c*32 + s2*16 + (i>>1)*8
    float2 ra[8];
#pragma unroll
    for (int s2 = 0; s2 < 2; ++s2) {
        ra[s2 * 4 + 0] = __ldcs((const float2*)(a0 + s2 * 16));
        ra[s2 * 4 + 1] = __ldcs((const float2*)(a1 + s2 * 16));
        ra[s2 * 4 + 2] = __ldcs((const float2*)(a0 + s2 * 16 + 8));
        ra[s2 * 4 + 3] = __ldcs((const float2*)(a1 + s2 * 16 + 8));
    }

#pragma unroll
    for (int c = 0; c < NCHUNK; ++c) {
        // convert current chunk to fp16 fragments
        uint32_t ha[8];
#pragma unroll
        for (int j = 0; j < 8; ++j) ha[j] = f2h2(ra[j]);

        // prefetch next chunk's raw A
        if (c + 1 < NCHUNK) {
            const int kb = (c + 1) * 32;
#pragma unroll
            for (int s2 = 0; s2 < 2; ++s2) {
                ra[s2 * 4 + 0] = __ldcs((const float2*)(a0 + kb + s2 * 16));
                ra[s2 * 4 + 1] = __ldcs((const float2*)(a1 + kb + s2 * 16));
                ra[s2 * 4 + 2] = __ldcs((const float2*)(a0 + kb + s2 * 16 + 8));
                ra[s2 * 4 + 3] = __ldcs((const float2*)(a1 + kb + s2 * 16 + 8));
            }
        }

        // B fragments: 4x LDG.128 per s2, then 8 MMAs
#pragma unroll
        for (int s2 = 0; s2 < 2; ++s2) {
            const uint4* bp = bBase + (size_t)((c * 2 + s2) * 2) * 32 * 4;
            uint4 b0 = __ldg(bp + 0), b1 = __ldg(bp + 1);
            uint4 b2 = __ldg(bp + 2), b3 = __ldg(bp + 3);
            uint32_t bb[16] = {b0.x, b0.y, b0.z, b0.w, b1.x, b1.y, b1.z, b1.w,
                               b2.x, b2.y, b2.z, b2.w, b3.x, b3.y, b3.z, b3.w};
#pragma unroll
            for (int nf = 0; nf < 8; ++nf)
                mma_f16(acc[nf], ha + s2 * 4, bb + nf * 2);
        }
    }

    // epilogue: scatter rows g and g+8 to out[loc0[.]]
    {
        int dst0 = __ldg(&loc0[rowbase]);
        int dst1 = __ldg(&loc0[rowbase + 8]);
        float* o0 = out + (size_t)dst0 * NDIM + wn * 64 + (lane & 3) * 2;
        float* o1 = out + (size_t)dst1 * NDIM + wn * 64 + (lane & 3) * 2;
#pragma unroll
        for (int nf = 0; nf < 8; ++nf)
            __stcs((float2*)(o0 + nf * 8), make_float2(acc[nf][0], acc[nf][1]));
#pragma unroll
        for (int nf = 0; nf < 8; ++nf)
            __stcs((float2*)(o1 + nf * 8), make_float2(acc[nf][2], acc[nf][3]));
    }
}

// --------------------------------------------------------------- launch
extern "C" void kernel_launch(void* const* d_in, const int* in_sizes, int n_in,
                              void* d_out, int out_size) {
    const int*   node_ids = (const int*)d_in[0];
    const int*   loc0     = (const int*)d_in[1];
    const int*   loc1     = (const int*)d_in[2];
    const int*   loc2     = (const int*)d_in[3];
    const float* feat0    = (const float*)d_in[4];
    const float* W0       = (const float*)d_in[5];
    const float* emb      = (const float*)d_in[6];
    float*       out      = (float*)d_out;

    int n1 = in_sizes[2];
    int n2 = in_sizes[3];

    convert_w_kernel<<<32768 / 256, 256>>>(W0);
    fused_kernel<<<GRID, 256>>>(feat0, loc0, node_ids, loc1, loc2, emb, out, n1, n2);
}

// round 9
// speedup vs baseline: 1.4540x; 1.4540x over previous
#include <cuda_runtime.h>
#include <cuda_fp16.h>
#include <cstdint>

// out[loc0]       = feat0 @ W0   (M=262144, K=512, N=128) fp16 mma.sync, err ~2.3e-4
// out[loc1++loc2] = emb[node_ids[loc]]
// Barrier-free GEMM: A via quad-pattern LDG.64 + cvt, B via lane-interleaved
// LDG.32 from a 128KB mma-ordered table (L1-resident, wavefront-optimal).
// Gather 8-deep (fits 80-reg budget at 3 CTAs/SM -- no local spills).

#define KDIM 512
#define NDIM 128
#define BM   64
#define NCHUNK 16                 // K chunks of 32
#define NGEMM 4096                // M/BM
#define GRID  (2 * NGEMM)

// B fragments in mma-ready order: idx = (s*16+f)*64 + r*32 + lane  (s = kstep 0..31)
// lane l, reg r holds B[k0+r*8+(l%4)*2+{0,1}][n0+l/4]
__device__ __align__(16) uint32_t g_Bfrag[32768];   // 128 KB, L1/L2-resident

// ------------------------------------------------------------- helpers
__device__ __forceinline__ void mma_f16(float* d, const uint32_t* a, const uint32_t* b) {
    asm volatile(
        "mma.sync.aligned.m16n8k16.row.col.f32.f16.f16.f32 "
        "{%0,%1,%2,%3}, {%4,%5,%6,%7}, {%8,%9}, {%0,%1,%2,%3};"
        : "+f"(d[0]), "+f"(d[1]), "+f"(d[2]), "+f"(d[3])
        : "r"(a[0]), "r"(a[1]), "r"(a[2]), "r"(a[3]), "r"(b[0]), "r"(b[1]));
}
__device__ __forceinline__ uint32_t f2h2(float2 v) {
    __half2 p = __floats2half2_rn(v.x, v.y);
    return *reinterpret_cast<uint32_t*>(&p);
}

// --------------------------------------------------- W0 -> fp16 fragment table
__global__ void convert_w_kernel(const float* __restrict__ W0) {
    int idx = blockIdx.x * 256 + threadIdx.x;   // 0..32767
    int l = idx & 31;
    int r = (idx >> 5) & 1;
    int f = (idx >> 6) & 15;
    int s = idx >> 10;                          // kstep 0..31
    int n = f * 8 + (l >> 2);
    int k = s * 16 + r * 8 + (l & 3) * 2;
    float x0 = W0[(size_t)k * NDIM + n];
    float x1 = W0[(size_t)(k + 1) * NDIM + n];
    __half2 p = __halves2half2(__float2half_rn(x0), __float2half_rn(x1));
    g_Bfrag[idx] = *reinterpret_cast<uint32_t*>(&p);
}

// --------------------------------------------------------------- fused kernel
__global__ void __launch_bounds__(256, 3)
fused_kernel(const float* __restrict__ feat0,
             const int* __restrict__ loc0,
             const int* __restrict__ node_ids,
             const int* __restrict__ loc1, const int* __restrict__ loc2,
             const float* __restrict__ emb,
             float* __restrict__ out,
             int n1, int n2) {
    const int tid  = threadIdx.x;
    const int wid  = tid >> 5;
    const int lane = tid & 31;

    if (blockIdx.x & 1) {
        // ===================== gather slice (8-deep MLP, no spills) ========
        const int ntot = n1 + n2;
        const int gb   = blockIdx.x >> 1;                 // 0..NGEMM-1
        const int rpb  = (ntot + NGEMM - 1) / NGEMM;      // rows per block (192)
        const int rpw  = (rpb + 7) / 8;                   // rows per warp (24)
        long rbase = (long)gb * rpb + (long)wid * rpw;
        for (int i = 0; i < rpw; i += 8) {
            int l[8];
#pragma unroll
            for (int r = 0; r < 8; r++) {
                long row = rbase + i + r;
                l[r] = (row < (long)ntot && (i + r) < rpw)
                         ? ((row < (long)n1) ? loc1[row] : loc2[row - n1]) : -1;
            }
            int nid[8];
#pragma unroll
            for (int r = 0; r < 8; r++) nid[r] = (l[r] >= 0) ? node_ids[l[r]] : 0;
            float4 v[8];
#pragma unroll
            for (int r = 0; r < 8; r++)
                if (l[r] >= 0)
                    v[r] = __ldcs(((const float4*)(emb + (size_t)nid[r] * NDIM)) + lane);
#pragma unroll
            for (int r = 0; r < 8; r++)
                if (l[r] >= 0)
                    __stcs(((float4*)(out + (size_t)l[r] * NDIM)) + lane, v[r]);
        }
        return;
    }

    // ========================= GEMM tile (64 x 128) ========================
    // 8 warps: wm = wid>>1 (0..3, 16 rows each), wn = wid&1 (0..1, 64 cols each)
    const int wm = wid >> 1;
    const int wn = wid & 1;
    const int m0 = (blockIdx.x >> 1) * BM;
    const int rowbase = m0 + wm * 16 + (lane >> 2);       // fragment row g

    // A row pointers for rows g and g+8, at k base (lane&3)*2
    const float* a0 = feat0 + (size_t)rowbase * KDIM + (lane & 3) * 2;
    const float* a1 = a0 + 8 * KDIM;

    float acc[8][4];
#pragma unroll
    for (int nf = 0; nf < 8; ++nf)
#pragma unroll
        for (int i = 0; i < 4; ++i) acc[nf][i] = 0.f;

    // raw A prefetch for chunk 0: [s2*4+i] with k = c*32 + s2*16 + (i>>1)*8
    float2 ra[8];
#pragma unroll
    for (int s2 = 0; s2 < 2; ++s2) {
        ra[s2 * 4 + 0] = __ldcs((const float2*)(a0 + s2 * 16));
        ra[s2 * 4 + 1] = __ldcs((const float2*)(a1 + s2 * 16));
        ra[s2 * 4 + 2] = __ldcs((const float2*)(a0 + s2 * 16 + 8));
        ra[s2 * 4 + 3] = __ldcs((const float2*)(a1 + s2 * 16 + 8));
    }

#pragma unroll
    for (int c = 0; c < NCHUNK; ++c) {
        // convert current chunk to fp16 fragments
        uint32_t ha[8];
#pragma unroll
        for (int j = 0; j < 8; ++j) ha[j] = f2h2(ra[j]);

        // prefetch next chunk's raw A
        if (c + 1 < NCHUNK) {
            const int kb = (c + 1) * 32;
#pragma unroll
            for (int s2 = 0; s2 < 2; ++s2) {
                ra[s2 * 4 + 0] = __ldcs((const float2*)(a0 + kb + s2 * 16));
                ra[s2 * 4 + 1] = __ldcs((const float2*)(a1 + kb + s2 * 16));
                ra[s2 * 4 + 2] = __ldcs((const float2*)(a0 + kb + s2 * 16 + 8));
                ra[s2 * 4 + 3] = __ldcs((const float2*)(a1 + kb + s2 * 16 + 8));
            }
        }

        // B fragments from L1-resident table (lane-interleaved) + 16 MMAs
        const uint32_t* Bc = g_Bfrag + c * 2048;
#pragma unroll
        for (int s2 = 0; s2 < 2; ++s2) {
#pragma unroll
            for (int nf = 0; nf < 8; ++nf) {
                const int fidx = s2 * 16 + wn * 8 + nf;
                uint32_t bh[2];
                bh[0] = __ldg(Bc + fidx * 64 + lane);
                bh[1] = __ldg(Bc + fidx * 64 + 32 + lane);
                mma_f16(acc[nf], ha + s2 * 4, bh);
            }
        }
    }

    // epilogue: scatter rows g and g+8 to out[loc0[.]]
    {
        int dst0 = __ldg(&loc0[rowbase]);
        int dst1 = __ldg(&loc0[rowbase + 8]);
        float* o0 = out + (size_t)dst0 * NDIM + wn * 64 + (lane & 3) * 2;
        float* o1 = out + (size_t)dst1 * NDIM + wn * 64 + (lane & 3) * 2;
#pragma unroll
        for (int nf = 0; nf < 8; ++nf)
            __stcs((float2*)(o0 + nf * 8), make_float2(acc[nf][0], acc[nf][1]));
#pragma unroll
        for (int nf = 0; nf < 8; ++nf)
            __stcs((float2*)(o1 + nf * 8), make_float2(acc[nf][2], acc[nf][3]));
    }
}

// --------------------------------------------------------------- launch
extern "C" void kernel_launch(void* const* d_in, const int* in_sizes, int n_in,
                              void* d_out, int out_size) {
    const int*   node_ids = (const int*)d_in[0];
    const int*   loc0     = (const int*)d_in[1];
    const int*   loc1     = (const int*)d_in[2];
    const int*   loc2     = (const int*)d_in[3];
    const float* feat0    = (const float*)d_in[4];
    const float* W0       = (const float*)d_in[5];
    const float* emb      = (const float*)d_in[6];
    float*       out      = (float*)d_out;

    int n1 = in_sizes[2];
    int n2 = in_sizes[3];

    convert_w_kernel<<<32768 / 256, 256>>>(W0);
    fused_kernel<<<GRID, 256>>>(feat0, loc0, node_ids, loc1, loc2, emb, out, n1, n2);
}

// round 10
// speedup vs baseline: 1.5685x; 1.0787x over previous
#include <cuda_runtime.h>
#include <cuda_fp16.h>
#include <cstdint>

// out[loc0]       = feat0 @ W0   (M=262144, K=512, N=128) fp16 mma.sync, err ~2.3e-4
// out[loc1++loc2] = emb[node_ids[loc]]
// k-permuted fragments: within each k16 mma step, lane l covers k=4*(l&3)+{0..3}
// (applied to BOTH A and B -> result identical). This makes every A and B load a
// full LDG.128: 12 memory instructions / 64 L1 wavefronts per warp-chunk
// (was 40 / 96). Barrier-free; B table L1-resident.

#define KDIM 512
#define NDIM 128
#define BM   64
#define NCHUNK 16                 // K chunks of 32
#define NGEMM 4096                // M/BM
#define GRID  (2 * NGEMM)

// B table: idx = (((s*2+wn)*4 + q)*32 + lane)*4 + w    (128 KB)
//   s = kstep 0..31, q = nf-pair 0..3, w: {nf=2q:r0, nf=2q:r1, nf=2q+1:r0, nf=2q+1:r1}
//   value: half2{ B[k][n], B[k+1][n] },  k = s*16 + (lane&3)*4 + r*2,
//          n = (wn*8 + nf)*8 + lane/4
__device__ __align__(16) uint32_t g_Bfrag[32768];

// ------------------------------------------------------------- helpers
__device__ __forceinline__ void mma_f16(float* d, const uint32_t* a,
                                        uint32_t b0, uint32_t b1) {
    asm volatile(
        "mma.sync.aligned.m16n8k16.row.col.f32.f16.f16.f32 "
        "{%0,%1,%2,%3}, {%4,%5,%6,%7}, {%8,%9}, {%0,%1,%2,%3};"
        : "+f"(d[0]), "+f"(d[1]), "+f"(d[2]), "+f"(d[3])
        : "r"(a[0]), "r"(a[1]), "r"(a[2]), "r"(a[3]), "r"(b0), "r"(b1));
}
__device__ __forceinline__ uint32_t f2h2(float x, float y) {
    __half2 p = __floats2half2_rn(x, y);
    return *reinterpret_cast<uint32_t*>(&p);
}

// --------------------------------------------------- W0 -> fp16 fragment table
__global__ void convert_w_kernel(const float* __restrict__ W0) {
    int idx = blockIdx.x * 256 + threadIdx.x;   // 0..32767
    int w    = idx & 3;
    int lane = (idx >> 2) & 31;
    int q    = (idx >> 7) & 3;
    int wn   = (idx >> 9) & 1;
    int s    = idx >> 10;                       // kstep 0..31
    int nf   = 2 * q + (w >> 1);
    int r    = w & 1;
    int n = (wn * 8 + nf) * 8 + (lane >> 2);
    int k = s * 16 + (lane & 3) * 4 + r * 2;    // k-permuted slot
    g_Bfrag[idx] = f2h2(W0[(size_t)k * NDIM + n], W0[(size_t)(k + 1) * NDIM + n]);
}

// --------------------------------------------------------------- fused kernel
__global__ void __launch_bounds__(256, 3)
fused_kernel(const float* __restrict__ feat0,
             const int* __restrict__ loc0,
             const int* __restrict__ node_ids,
             const int* __restrict__ loc1, const int* __restrict__ loc2,
             const float* __restrict__ emb,
             float* __restrict__ out,
             int n1, int n2) {
    const int tid  = threadIdx.x;
    const int wid  = tid >> 5;
    const int lane = tid & 31;

    if (blockIdx.x & 1) {
        // ===================== gather slice (8-deep MLP) ===================
        const int ntot = n1 + n2;
        const int gb   = blockIdx.x >> 1;                 // 0..NGEMM-1
        const int rpb  = (ntot + NGEMM - 1) / NGEMM;      // rows per block (192)
        const int rpw  = (rpb + 7) / 8;                   // rows per warp (24)
        long rbase = (long)gb * rpb + (long)wid * rpw;
        for (int i = 0; i < rpw; i += 8) {
            int l[8];
#pragma unroll
            for (int r = 0; r < 8; r++) {
                long row = rbase + i + r;
                l[r] = (row < (long)ntot && (i + r) < rpw)
                         ? ((row < (long)n1) ? loc1[row] : loc2[row - n1]) : -1;
            }
            int nid[8];
#pragma unroll
            for (int r = 0; r < 8; r++) nid[r] = (l[r] >= 0) ? node_ids[l[r]] : 0;
            float4 v[8];
#pragma unroll
            for (int r = 0; r < 8; r++)
                if (l[r] >= 0)
                    v[r] = __ldcs(((const float4*)(emb + (size_t)nid[r] * NDIM)) + lane);
#pragma unroll
            for (int r = 0; r < 8; r++)
                if (l[r] >= 0)
                    __stcs(((float4*)(out + (size_t)l[r] * NDIM)) + lane, v[r]);
        }
        return;
    }

    // ========================= GEMM tile (64 x 128) ========================
    // 8 warps: wm = wid>>1 (0..3, 16 rows each), wn = wid&1 (0..1, 64 cols each)
    const int wm = wid >> 1;
    const int wn = wid & 1;
    const int m0 = (blockIdx.x >> 1) * BM;
    const int rowbase = m0 + wm * 16 + (lane >> 2);       // fragment row g

    // A row pointers for rows g and g+8, at permuted k base (lane&3)*4
    const float* a0 = feat0 + (size_t)rowbase * KDIM + (lane & 3) * 4;
    const float* a1 = a0 + 8 * KDIM;
    // per-lane B table base for this warp's wn half (uint4 units)
    const uint4* bTab = (const uint4*)g_Bfrag + (size_t)wn * 4 * 32 + lane;

    float acc[8][4];
#pragma unroll
    for (int nf = 0; nf < 8; ++nf)
#pragma unroll
        for (int i = 0; i < 4; ++i) acc[nf][i] = 0.f;

    // raw A prefetch for chunk 0: ra[s2*2 + row] (row: 0=g, 1=g+8)
    float4 ra[4];
    ra[0] = __ldcs((const float4*)(a0));
    ra[1] = __ldcs((const float4*)(a1));
    ra[2] = __ldcs((const float4*)(a0 + 16));
    ra[3] = __ldcs((const float4*)(a1 + 16));

#pragma unroll
    for (int c = 0; c < NCHUNK; ++c) {
        // convert current chunk: frag order {(g,klo),(g+8,klo),(g,khi),(g+8,khi)}
        uint32_t ha[2][4];
#pragma unroll
        for (int s2 = 0; s2 < 2; ++s2) {
            ha[s2][0] = f2h2(ra[s2 * 2 + 0].x, ra[s2 * 2 + 0].y);
            ha[s2][1] = f2h2(ra[s2 * 2 + 1].x, ra[s2 * 2 + 1].y);
            ha[s2][2] = f2h2(ra[s2 * 2 + 0].z, ra[s2 * 2 + 0].w);
            ha[s2][3] = f2h2(ra[s2 * 2 + 1].z, ra[s2 * 2 + 1].w);
        }

        // prefetch next chunk's raw A
        if (c + 1 < NCHUNK) {
            const int kb = (c + 1) * 32;
            ra[0] = __ldcs((const float4*)(a0 + kb));
            ra[1] = __ldcs((const float4*)(a1 + kb));
            ra[2] = __ldcs((const float4*)(a0 + kb + 16));
            ra[3] = __ldcs((const float4*)(a1 + kb + 16));
        }

        // B: 4x LDG.128 per s2 (contiguous 512B per instr), 8 MMAs per s2
#pragma unroll
        for (int s2 = 0; s2 < 2; ++s2) {
            const uint4* bp = bTab + (size_t)((c * 2 + s2) * 2) * 4 * 32;
            uint4 q0 = __ldg(bp);
            uint4 q1 = __ldg(bp + 32);
            uint4 q2 = __ldg(bp + 64);
            uint4 q3 = __ldg(bp + 96);
            mma_f16(acc[0], ha[s2], q0.x, q0.y);
            mma_f16(acc[1], ha[s2], q0.z, q0.w);
            mma_f16(acc[2], ha[s2], q1.x, q1.y);
            mma_f16(acc[3], ha[s2], q1.z, q1.w);
            mma_f16(acc[4], ha[s2], q2.x, q2.y);
            mma_f16(acc[5], ha[s2], q2.z, q2.w);
            mma_f16(acc[6], ha[s2], q3.x, q3.y);
            mma_f16(acc[7], ha[s2], q3.z, q3.w);
        }
    }

    // epilogue: scatter rows g and g+8 to out[loc0[.]]
    {
        int dst0 = __ldg(&loc0[rowbase]);
        int dst1 = __ldg(&loc0[rowbase + 8]);
        float* o0 = out + (size_t)dst0 * NDIM + wn * 64 + (lane & 3) * 2;
        float* o1 = out + (size_t)dst1 * NDIM + wn * 64 + (lane & 3) * 2;
#pragma unroll
        for (int nf = 0; nf < 8; ++nf)
            __stcs((float2*)(o0 + nf * 8), make_float2(acc[nf][0], acc[nf][1]));
#pragma unroll
        for (int nf = 0; nf < 8; ++nf)
            __stcs((float2*)(o1 + nf * 8), make_float2(acc[nf][2], acc[nf][3]));
    }
}

// --------------------------------------------------------------- launch
extern "C" void kernel_launch(void* const* d_in, const int* in_sizes, int n_in,
                              void* d_out, int out_size) {
    const int*   node_ids = (const int*)d_in[0];
    const int*   loc0     = (const int*)d_in[1];
    const int*   loc1     = (const int*)d_in[2];
    const int*   loc2     = (const int*)d_in[3];
    const float* feat0    = (const float*)d_in[4];
    const float* W0       = (const float*)d_in[5];
    const float* emb      = (const float*)d_in[6];
    float*       out      = (float*)d_out;

    int n1 = in_sizes[2];
    int n2 = in_sizes[3];

    convert_w_kernel<<<32768 / 256, 256>>>(W0);
    fused_kernel<<<GRID, 256>>>(feat0, loc0, node_ids, loc1, loc2, emb, out, n1, n2);
}

// round 11
// speedup vs baseline: 1.6389x; 1.0449x over previous
#include <cuda_runtime.h>
#include <cuda_fp16.h>
#include <cstdint>

// out[loc0]       = feat0 @ W0   (M=262144, K=512, N=128) fp16 mma.sync, err ~2.3e-4
// out[loc1++loc2] = emb[node_ids[loc]]
// GEMM: k-permuted fragments, all LDG.128, barrier-free (R10 design).
// Gather: index chain (loc -> node_ids) software-pipelined one batch ahead so
// uniform index loads overlap the 8 in-flight row loads.

#define KDIM 512
#define NDIM 128
#define BM   64
#define NCHUNK 16                 // K chunks of 32
#define NGEMM 4096                // M/BM
#define GRID  (2 * NGEMM)

// B table: idx = (((s*2+wn)*4 + q)*32 + lane)*4 + w    (128 KB)
//   value: half2{ B[k][n], B[k+1][n] },  k = s*16 + (lane&3)*4 + r*2 (k-permuted),
//          n = (wn*8 + 2q + (w>>1))*8 + lane/4,  r = w&1
__device__ __align__(16) uint32_t g_Bfrag[32768];

// ------------------------------------------------------------- helpers
__device__ __forceinline__ void mma_f16(float* d, const uint32_t* a,
                                        uint32_t b0, uint32_t b1) {
    asm volatile(
        "mma.sync.aligned.m16n8k16.row.col.f32.f16.f16.f32 "
        "{%0,%1,%2,%3}, {%4,%5,%6,%7}, {%8,%9}, {%0,%1,%2,%3};"
        : "+f"(d[0]), "+f"(d[1]), "+f"(d[2]), "+f"(d[3])
        : "r"(a[0]), "r"(a[1]), "r"(a[2]), "r"(a[3]), "r"(b0), "r"(b1));
}
__device__ __forceinline__ uint32_t f2h2(float x, float y) {
    __half2 p = __floats2half2_rn(x, y);
    return *reinterpret_cast<uint32_t*>(&p);
}

// --------------------------------------------------- W0 -> fp16 fragment table
__global__ void convert_w_kernel(const float* __restrict__ W0) {
    int idx = blockIdx.x * 256 + threadIdx.x;   // 0..32767
    int w    = idx & 3;
    int lane = (idx >> 2) & 31;
    int q    = (idx >> 7) & 3;
    int wn   = (idx >> 9) & 1;
    int s    = idx >> 10;                       // kstep 0..31
    int nf   = 2 * q + (w >> 1);
    int r    = w & 1;
    int n = (wn * 8 + nf) * 8 + (lane >> 2);
    int k = s * 16 + (lane & 3) * 4 + r * 2;    // k-permuted slot
    g_Bfrag[idx] = f2h2(W0[(size_t)k * NDIM + n], W0[(size_t)(k + 1) * NDIM + n]);
}

// --------------------------------------------------------------- fused kernel
__global__ void __launch_bounds__(256, 3)
fused_kernel(const float* __restrict__ feat0,
             const int* __restrict__ loc0,
             const int* __restrict__ node_ids,
             const int* __restrict__ loc1, const int* __restrict__ loc2,
             const float* __restrict__ emb,
             float* __restrict__ out,
             int n1, int n2) {
    const int tid  = threadIdx.x;
    const int wid  = tid >> 5;
    const int lane = tid & 31;

    if (blockIdx.x & 1) {
        // ============ gather slice: pipelined index chain ==================
        const int ntot = n1 + n2;
        const int gb   = blockIdx.x >> 1;                 // 0..NGEMM-1
        const int rpb  = (ntot + NGEMM - 1) / NGEMM;      // rows per block (192)
        const int rpw  = (rpb + 7) / 8;                   // rows per warp (24)
        long rbase = (long)gb * rpb + (long)wid * rpw;

        int l[8], nid[8];
#pragma unroll
        for (int r = 0; r < 8; r++) {
            long row = rbase + r;
            l[r] = (row < (long)ntot && r < rpw)
                     ? ((row < (long)n1) ? __ldg(loc1 + row) : __ldg(loc2 + row - n1))
                     : -1;
        }
#pragma unroll
        for (int r = 0; r < 8; r++)
            nid[r] = (l[r] >= 0) ? __ldg(node_ids + l[r]) : 0;

        for (int i = 0; i < rpw; i += 8) {
            int lc[8], nc[8];
#pragma unroll
            for (int r = 0; r < 8; r++) { lc[r] = l[r]; nc[r] = nid[r]; }

            // issue current batch's row loads (8 in flight)
            float4 v[8];
#pragma unroll
            for (int r = 0; r < 8; r++)
                if (lc[r] >= 0)
                    v[r] = __ldcs(((const float4*)(emb + (size_t)nc[r] * NDIM)) + lane);

            // prefetch next batch's index chain while rows are in flight
            if (i + 8 < rpw) {
#pragma unroll
                for (int r = 0; r < 8; r++) {
                    long row = rbase + i + 8 + r;
                    l[r] = (row < (long)ntot && (i + 8 + r) < rpw)
                             ? ((row < (long)n1) ? __ldg(loc1 + row)
                                                 : __ldg(loc2 + row - n1))
                             : -1;
                }
#pragma unroll
                for (int r = 0; r < 8; r++)
                    nid[r] = (l[r] >= 0) ? __ldg(node_ids + l[r]) : 0;
            }

            // drain current batch
#pragma unroll
            for (int r = 0; r < 8; r++)
                if (lc[r] >= 0)
                    __stcs(((float4*)(out + (size_t)lc[r] * NDIM)) + lane, v[r]);
        }
        return;
    }

    // ========================= GEMM tile (64 x 128) ========================
    const int wm = wid >> 1;
    const int wn = wid & 1;
    const int m0 = (blockIdx.x >> 1) * BM;
    const int rowbase = m0 + wm * 16 + (lane >> 2);       // fragment row g

    const float* a0 = feat0 + (size_t)rowbase * KDIM + (lane & 3) * 4;
    const float* a1 = a0 + 8 * KDIM;
    const uint4* bTab = (const uint4*)g_Bfrag + (size_t)wn * 4 * 32 + lane;

    float acc[8][4];
#pragma unroll
    for (int nf = 0; nf < 8; ++nf)
#pragma unroll
        for (int i = 0; i < 4; ++i) acc[nf][i] = 0.f;

    float4 ra[4];
    ra[0] = __ldcs((const float4*)(a0));
    ra[1] = __ldcs((const float4*)(a1));
    ra[2] = __ldcs((const float4*)(a0 + 16));
    ra[3] = __ldcs((const float4*)(a1 + 16));

#pragma unroll
    for (int c = 0; c < NCHUNK; ++c) {
        uint32_t ha[2][4];
#pragma unroll
        for (int s2 = 0; s2 < 2; ++s2) {
            ha[s2][0] = f2h2(ra[s2 * 2 + 0].x, ra[s2 * 2 + 0].y);
            ha[s2][1] = f2h2(ra[s2 * 2 + 1].x, ra[s2 * 2 + 1].y);
            ha[s2][2] = f2h2(ra[s2 * 2 + 0].z, ra[s2 * 2 + 0].w);
            ha[s2][3] = f2h2(ra[s2 * 2 + 1].z, ra[s2 * 2 + 1].w);
        }

        if (c + 1 < NCHUNK) {
            const int kb = (c + 1) * 32;
            ra[0] = __ldcs((const float4*)(a0 + kb));
            ra[1] = __ldcs((const float4*)(a1 + kb));
            ra[2] = __ldcs((const float4*)(a0 + kb + 16));
            ra[3] = __ldcs((const float4*)(a1 + kb + 16));
        }

#pragma unroll
        for (int s2 = 0; s2 < 2; ++s2) {
            const uint4* bp = bTab + (size_t)((c * 2 + s2) * 2) * 4 * 32;
            uint4 q0 = __ldg(bp);
            uint4 q1 = __ldg(bp + 32);
            uint4 q2 = __ldg(bp + 64);
            uint4 q3 = __ldg(bp + 96);
            mma_f16(acc[0], ha[s2], q0.x, q0.y);
            mma_f16(acc[1], ha[s2], q0.z, q0.w);
            mma_f16(acc[2], ha[s2], q1.x, q1.y);
            mma_f16(acc[3], ha[s2], q1.z, q1.w);
            mma_f16(acc[4], ha[s2], q2.x, q2.y);
            mma_f16(acc[5], ha[s2], q2.z, q2.w);
            mma_f16(acc[6], ha[s2], q3.x, q3.y);
            mma_f16(acc[7], ha[s2], q3.z, q3.w);
        }
    }

    // epilogue: scatter rows g and g+8 to out[loc0[.]]
    {
        int dst0 = __ldg(&loc0[rowbase]);
        int dst1 = __ldg(&loc0[rowbase + 8]);
        float* o0 = out + (size_t)dst0 * NDIM + wn * 64 + (lane & 3) * 2;
        float* o1 = out + (size_t)dst1 * NDIM + wn * 64 + (lane & 3) * 2;
#pragma unroll
        for (int nf = 0; nf < 8; ++nf)
            __stcs((float2*)(o0 + nf * 8), make_float2(acc[nf][0], acc[nf][1]));
#pragma unroll
        for (int nf = 0; nf < 8; ++nf)
            __stcs((float2*)(o1 + nf * 8), make_float2(acc[nf][2], acc[nf][3]));
    }
}

// --------------------------------------------------------------- launch
extern "C" void kernel_launch(void* const* d_in, const int* in_sizes, int n_in,
                              void* d_out, int out_size) {
    const int*   node_ids = (const int*)d_in[0];
    const int*   loc0     = (const int*)d_in[1];
    const int*   loc1     = (const int*)d_in[2];
    const int*   loc2     = (const int*)d_in[3];
    const float* feat0    = (const float*)d_in[4];
    const float* W0       = (const float*)d_in[5];
    const float* emb      = (const float*)d_in[6];
    float*       out      = (float*)d_out;

    int n1 = in_sizes[2];
    int n2 = in_sizes[3];

    convert_w_kernel<<<32768 / 256, 256>>>(W0);
    fused_kernel<<<GRID, 256>>>(feat0, loc0, node_ids, loc1, loc2, emb, out, n1, n2);
}

// round 12
// speedup vs baseline: 1.7501x; 1.0679x over previous
#include <cuda_runtime.h>
#include <cuda_fp16.h>
#include <cstdint>

// out[loc0]       = feat0 @ W0   (M=262144, K=512, N=128) fp16 mma.sync, err ~2.3e-4
// out[loc1++loc2] = emb[node_ids[loc]]
// GEMM: A streamed via 4-stage cp.async.cg pipeline (3 chunks in flight, 24KB),
//       XOR-swizzled smem, k-permuted fragments; B via LDG.128 from an
//       L1-resident mma-ordered table. Gather: pipelined index chain (R11).

#define KDIM 512
#define NDIM 128
#define BM   64
#define NCHUNK 16                 // K chunks of 32 floats (128B per row)
#define NSTAGE 4
#define STAGE_B 8192              // 64 rows x 128B
#define SMEM_B (NSTAGE * STAGE_B) // 32 KB
#define NGEMM 4096                // M/BM
#define GRID  (2 * NGEMM)

// B table: idx = (((s*2+wn)*4 + q)*32 + lane)*4 + w    (128 KB)
//   value: half2{ B[k][n], B[k+1][n] },  k = s*16 + (lane&3)*4 + r*2 (k-permuted),
//          n = (wn*8 + 2q + (w>>1))*8 + lane/4,  r = w&1
__device__ __align__(16) uint32_t g_Bfrag[32768];

// ------------------------------------------------------------- helpers
__device__ __forceinline__ uint32_t smem_u32(const void* p) {
    uint32_t a;
    asm("{ .reg .u64 t; cvta.to.shared.u64 t, %1; cvt.u32.u64 %0, t; }"
        : "=r"(a) : "l"(p));
    return a;
}
__device__ __forceinline__ void cp16(uint32_t dst, const void* src) {
    asm volatile("cp.async.cg.shared.global [%0], [%1], 16;"
                 :: "r"(dst), "l"(src) : "memory");
}
__device__ __forceinline__ void mma_f16(float* d, const uint32_t* a,
                                        uint32_t b0, uint32_t b1) {
    asm volatile(
        "mma.sync.aligned.m16n8k16.row.col.f32.f16.f16.f32 "
        "{%0,%1,%2,%3}, {%4,%5,%6,%7}, {%8,%9}, {%0,%1,%2,%3};"
        : "+f"(d[0]), "+f"(d[1]), "+f"(d[2]), "+f"(d[3])
        : "r"(a[0]), "r"(a[1]), "r"(a[2]), "r"(a[3]), "r"(b0), "r"(b1));
}
__device__ __forceinline__ uint32_t f2h2(float x, float y) {
    __half2 p = __floats2half2_rn(x, y);
    return *reinterpret_cast<uint32_t*>(&p);
}

// --------------------------------------------------- W0 -> fp16 fragment table
__global__ void convert_w_kernel(const float* __restrict__ W0) {
    int idx = blockIdx.x * 256 + threadIdx.x;   // 0..32767
    int w    = idx & 3;
    int lane = (idx >> 2) & 31;
    int q    = (idx >> 7) & 3;
    int wn   = (idx >> 9) & 1;
    int s    = idx >> 10;                       // kstep 0..31
    int nf   = 2 * q + (w >> 1);
    int r    = w & 1;
    int n = (wn * 8 + nf) * 8 + (lane >> 2);
    int k = s * 16 + (lane & 3) * 4 + r * 2;    // k-permuted slot
    g_Bfrag[idx] = f2h2(W0[(size_t)k * NDIM + n], W0[(size_t)(k + 1) * NDIM + n]);
}

// --------------------------------------------------------------- fused kernel
__global__ void __launch_bounds__(256, 3)
fused_kernel(const float* __restrict__ feat0,
             const int* __restrict__ loc0,
             const int* __restrict__ node_ids,
             const int* __restrict__ loc1, const int* __restrict__ loc2,
             const float* __restrict__ emb,
             float* __restrict__ out,
             int n1, int n2) {
    extern __shared__ char smem[];
    const int tid  = threadIdx.x;
    const int wid  = tid >> 5;
    const int lane = tid & 31;

    if (blockIdx.x & 1) {
        // ============ gather slice: pipelined index chain (R11) ============
        const int ntot = n1 + n2;
        const int gb   = blockIdx.x >> 1;                 // 0..NGEMM-1
        const int rpb  = (ntot + NGEMM - 1) / NGEMM;      // rows per block (192)
        const int rpw  = (rpb + 7) / 8;                   // rows per warp (24)
        long rbase = (long)gb * rpb + (long)wid * rpw;

        int l[8], nid[8];
#pragma unroll
        for (int r = 0; r < 8; r++) {
            long row = rbase + r;
            l[r] = (row < (long)ntot && r < rpw)
                     ? ((row < (long)n1) ? __ldg(loc1 + row) : __ldg(loc2 + row - n1))
                     : -1;
        }
#pragma unroll
        for (int r = 0; r < 8; r++)
            nid[r] = (l[r] >= 0) ? __ldg(node_ids + l[r]) : 0;

        for (int i = 0; i < rpw; i += 8) {
            int lc[8], nc[8];
#pragma unroll
            for (int r = 0; r < 8; r++) { lc[r] = l[r]; nc[r] = nid[r]; }

            float4 v[8];
#pragma unroll
            for (int r = 0; r < 8; r++)
                if (lc[r] >= 0)
                    v[r] = __ldcs(((const float4*)(emb + (size_t)nc[r] * NDIM)) + lane);

            if (i + 8 < rpw) {
#pragma unroll
                for (int r = 0; r < 8; r++) {
                    long row = rbase + i + 8 + r;
                    l[r] = (row < (long)ntot && (i + 8 + r) < rpw)
                             ? ((row < (long)n1) ? __ldg(loc1 + row)
                                                 : __ldg(loc2 + row - n1))
                             : -1;
                }
#pragma unroll
                for (int r = 0; r < 8; r++)
                    nid[r] = (l[r] >= 0) ? __ldg(node_ids + l[r]) : 0;
            }

#pragma unroll
            for (int r = 0; r < 8; r++)
                if (lc[r] >= 0)
                    __stcs(((float4*)(out + (size_t)lc[r] * NDIM)) + lane, v[r]);
        }
        return;
    }

    // ========================= GEMM tile (64 x 128) ========================
    const int wm = wid >> 1;
    const int wn = wid & 1;
    const int m0 = (blockIdx.x >> 1) * BM;
    const int rowbase = m0 + wm * 16 + (lane >> 2);       // fragment row g
    const uint32_t sbase = smem_u32(smem);

    // cp.async thread mapping: idx = tid + j*256 covers (row = idx>>3, unit = idx&7)
    // 8 lanes cover one 128B row contiguously (coalesced); unit XOR-swizzled.
    const int arow  = tid >> 3;              // rows 0..31 (j=0), 32..63 (j=1)
    const int aunit = tid & 7;
    const uint32_t aphys0 = (uint32_t)(arow * 128 + ((aunit ^ ((arow & 1) << 2)) * 16));
    const uint32_t aphys1 = (uint32_t)((arow + 32) * 128 +
                                       ((aunit ^ (((arow + 32) & 1) << 2)) * 16));
    const float* asrc0 = feat0 + (size_t)(m0 + arow) * KDIM + aunit * 4;
    const float* asrc1 = feat0 + (size_t)(m0 + arow + 32) * KDIM + aunit * 4;

    // fragment LDS offsets (k-permuted): unit u = (lane&3) + 4*s2, row g / g+8
    const int r0 = wm * 16 + (lane >> 2);
    const int par = (r0 & 1) << 2;
    const uint32_t lds_r0_s0 = (uint32_t)(r0 * 128 + (((lane & 3) + 0) ^ par) * 16);
    const uint32_t lds_r0_s1 = (uint32_t)(r0 * 128 + (((lane & 3) + 4) ^ par) * 16);
    const uint32_t lds_r1_s0 = lds_r0_s0 + 8 * 128;
    const uint32_t lds_r1_s1 = lds_r0_s1 + 8 * 128;

    const uint4* bTab = (const uint4*)g_Bfrag + (size_t)wn * 4 * 32 + lane;

    float acc[8][4];
#pragma unroll
    for (int nf = 0; nf < 8; ++nf)
#pragma unroll
        for (int i = 0; i < 4; ++i) acc[nf][i] = 0.f;

    // prologue: issue stages 0..2
#pragma unroll
    for (int n = 0; n < NSTAGE - 1; ++n) {
        uint32_t sb = sbase + n * STAGE_B;
        cp16(sb + aphys0, asrc0 + n * 32);
        cp16(sb + aphys1, asrc1 + n * 32);
        asm volatile("cp.async.commit_group;" ::: "memory");
    }

#pragma unroll
    for (int c = 0; c < NCHUNK; ++c) {
        asm volatile("cp.async.wait_group %0;" :: "n"(NSTAGE - 2) : "memory");
        __syncthreads();

        const char* stage = smem + (c & (NSTAGE - 1)) * STAGE_B;

        // LDS raw fp32 fragments (conflict-free) and convert
        float4 f00 = *(const float4*)(stage + lds_r0_s0);
        float4 f10 = *(const float4*)(stage + lds_r1_s0);
        float4 f01 = *(const float4*)(stage + lds_r0_s1);
        float4 f11 = *(const float4*)(stage + lds_r1_s1);
        uint32_t ha[2][4];
        ha[0][0] = f2h2(f00.x, f00.y); ha[0][1] = f2h2(f10.x, f10.y);
        ha[0][2] = f2h2(f00.z, f00.w); ha[0][3] = f2h2(f10.z, f10.w);
        ha[1][0] = f2h2(f01.x, f01.y); ha[1][1] = f2h2(f11.x, f11.y);
        ha[1][2] = f2h2(f01.z, f01.w); ha[1][3] = f2h2(f11.z, f11.w);

        // issue stage c+3 (slot (c-1)&3; all warps finished compute(c-1) at sync)
        if (c + NSTAGE - 1 < NCHUNK) {
            const int n = c + NSTAGE - 1;
            uint32_t sb = sbase + (n & (NSTAGE - 1)) * STAGE_B;
            cp16(sb + aphys0, asrc0 + n * 32);
            cp16(sb + aphys1, asrc1 + n * 32);
        }
        asm volatile("cp.async.commit_group;" ::: "memory");

        // B fragments + 16 MMAs
#pragma unroll
        for (int s2 = 0; s2 < 2; ++s2) {
            const uint4* bp = bTab + (size_t)((c * 2 + s2) * 2) * 4 * 32;
            uint4 q0 = __ldg(bp);
            uint4 q1 = __ldg(bp + 32);
            uint4 q2 = __ldg(bp + 64);
            uint4 q3 = __ldg(bp + 96);
            mma_f16(acc[0], ha[s2], q0.x, q0.y);
            mma_f16(acc[1], ha[s2], q0.z, q0.w);
            mma_f16(acc[2], ha[s2], q1.x, q1.y);
            mma_f16(acc[3], ha[s2], q1.z, q1.w);
            mma_f16(acc[4], ha[s2], q2.x, q2.y);
            mma_f16(acc[5], ha[s2], q2.z, q2.w);
            mma_f16(acc[6], ha[s2], q3.x, q3.y);
            mma_f16(acc[7], ha[s2], q3.z, q3.w);
        }
    }

    // epilogue: scatter rows g and g+8 to out[loc0[.]]
    {
        int dst0 = __ldg(&loc0[rowbase]);
        int dst1 = __ldg(&loc0[rowbase + 8]);
        float* o0 = out + (size_t)dst0 * NDIM + wn * 64 + (lane & 3) * 2;
        float* o1 = out + (size_t)dst1 * NDIM + wn * 64 + (lane & 3) * 2;
#pragma unroll
        for (int nf = 0; nf < 8; ++nf)
            __stcs((float2*)(o0 + nf * 8), make_float2(acc[nf][0], acc[nf][1]));
#pragma unroll
        for (int nf = 0; nf < 8; ++nf)
            __stcs((float2*)(o1 + nf * 8), make_float2(acc[nf][2], acc[nf][3]));
    }
}

// --------------------------------------------------------------- launch
extern "C" void kernel_launch(void* const* d_in, const int* in_sizes, int n_in,
                              void* d_out, int out_size) {
    const int*   node_ids = (const int*)d_in[0];
    const int*   loc0     = (const int*)d_in[1];
    const int*   loc1     = (const int*)d_in[2];
    const int*   loc2     = (const int*)d_in[3];
    const float* feat0    = (const float*)d_in[4];
    const float* W0       = (const float*)d_in[5];
    const float* emb      = (const float*)d_in[6];
    float*       out      = (float*)d_out;

    int n1 = in_sizes[2];
    int n2 = in_sizes[3];

    cudaFuncSetAttribute(fused_kernel,
                         cudaFuncAttributeMaxDynamicSharedMemorySize, SMEM_B);

    convert_w_kernel<<<32768 / 256, 256>>>(W0);
    fused_kernel<<<GRID, 256, SMEM_B>>>(feat0, loc0, node_ids, loc1, loc2,
                                        emb, out, n1, n2);
}